// round 14
// baseline (speedup 1.0000x reference)
#include <cuda_runtime.h>

#define RES 128
#define IMG 480
#define NBATCH 16

#define CACHE_W 84       // max unaligned window width (validity check)
#define CACHE_H 74
#define CACHE_PITCH 84   // mult of 4 (16B rows); bank stride 20 mod 32 -> cycle 8

// Block: fixed b; ix in [ixo*32,+32), iz in [izo*32,+32), iy in [iyo*32,+32).
// 1024 blocks = 148 SMs x 8 resident -> ONE wave, no tail.
// Thread: ix = ixo*32 + w*4 + (lane>>3); iz quad = izo*32 + (lane&7)*4 .. +3.
// 128 voxels/thread: prologue (4 IEEE divides, corner bounds, window fill)
// amortized 4x vs the 8-iy version. Inner loop identical to R12.

__global__ __launch_bounds__(256, 8)
void backproj_kernel(const float* __restrict__ depth,
                     const float* __restrict__ fl_arr,
                     const float* __restrict__ cd_arr,
                     float* __restrict__ out)
{
    __shared__ float win[CACHE_H * CACHE_PITCH];

    const int bid = blockIdx.x;          // 1024 blocks
    const int izo = bid & 3;
    const int ixo = (bid >> 2) & 3;
    const int iyo = (bid >> 4) & 3;
    const int b   = bid >> 6;

    const int tid  = threadIdx.x;
    const int lane = tid & 31;
    const int w    = tid >> 5;           // 0..7

    const float inv_res = 1.0f / (float)RES;
    const float off   = (IMG - 1) * 0.5f;   // 239.5
    const float wmax  = (float)(IMG - 1);   // 479
    const float trunc = inv_res;            // h = 1/128

    const float fl = __ldg(fl_arr + b);
    const float cd = __ldg(cd_arr + b);

    const int ix  = ixo * 32 + w * 4 + (lane >> 3);
    const int izb = izo * 32 + (lane & 7) * 4;
    const int iy0 = iyo * 32;

    // ---- per-thread prologue: 4 consecutive iz ----
    const float flx = fl * (((float)ix + 0.5f) * inv_res - 0.5f);
    const float zc0 = cd - (((float)izb + 0.5f) * inv_res - 0.5f);  // zc[k] = zc0 - k*h
    float izc[4];
    int   ui[4];
    #pragma unroll
    for (int k = 0; k < 4; k++) {
        izc[k] = 1.0f / (zc0 - (float)k * inv_res);
        ui[k]  = __float2int_rn(flx * izc[k] + off);
    }

    // ---- block-uniform corner bounds ----
    const float cx_lo = ((float)(ixo * 32)      + 0.5f) * inv_res - 0.5f;
    const float cx_hi = ((float)(ixo * 32 + 31) + 0.5f) * inv_res - 0.5f;
    const float cy_lo = ((float)(iy0)           + 0.5f) * inv_res - 0.5f;
    const float cy_hi = ((float)(iy0 + 31)      + 0.5f) * inv_res - 0.5f;
    const float zc_a  = cd - (((float)(izo * 32)      + 0.5f) * inv_res - 0.5f);
    const float zc_b  = cd - (((float)(izo * 32 + 31) + 0.5f) * inv_res - 0.5f);
    const float ia = 1.0f / zc_a, ib = 1.0f / zc_b;

    float u00 = fl * cx_lo * ia + off, u01 = fl * cx_lo * ib + off;
    float u10 = fl * cx_hi * ia + off, u11 = fl * cx_hi * ib + off;
    float v00 = fl * cy_lo * ia + off, v01 = fl * cy_lo * ib + off;
    float v10 = fl * cy_hi * ia + off, v11 = fl * cy_hi * ib + off;

    float umin = fminf(fminf(u00, u01), fminf(u10, u11));
    float umax = fmaxf(fmaxf(u00, u01), fmaxf(u10, u11));
    float vmin = fminf(fminf(v00, v01), fminf(v10, v11));
    float vmax = fmaxf(fmaxf(v00, v01), fmaxf(v10, v11));

    int u0 = max(0, (int)floorf(umin) - 1);
    int u1 = min(IMG - 1, (int)ceilf(umax) + 1);
    int v0 = max(0, (int)floorf(vmin) - 1);
    int v1 = min(IMG - 1, (int)ceilf(vmax) + 1);
    const int Wd = u1 - u0 + 1;
    const int Hd = v1 - v0 + 1;

    const bool all_valid =
        (fminf(zc_a, zc_b) > trunc) &
        (umin >= 0.01f) & (umax <= wmax - 0.01f) &
        (vmin >= 0.01f) & (vmax <= wmax - 0.01f) &
        (Wd <= CACHE_W) & (Hd <= CACHE_H);

    const float* __restrict__ ds = depth + (size_t)b * (IMG * IMG);
    float* __restrict__ ob = out + (((size_t)(b * RES + ix)) * RES + iy0) * RES + izb;

    if (all_valid) {
        // ---- float4 window fill: u0 aligned down to 4; warp per row stripe ----
        const int u0a = u0 & ~3;                     // 16B-aligned start
        const int W4  = (u1 - u0a + 4) >> 2;         // float4 count (<=20)
        for (int r = w; r < Hd; r += 8) {
            const float4* src = reinterpret_cast<const float4*>(ds + (v0 + r) * IMG + u0a);
            float4* dst = reinterpret_cast<float4*>(win + r * CACHE_PITCH);
            if (lane < W4) dst[lane] = __ldg(src + lane);
        }
        __syncthreads();

        // precomputed smem pointers: gather addr = wp[k] + vi*CACHE_PITCH
        const float* wp[4];
        #pragma unroll
        for (int k = 0; k < 4; k++)
            wp[k] = win + ((ui[k] - u0a) - v0 * CACHE_PITCH);

        float fly = fl * (((float)iy0 + 0.5f) * inv_res - 0.5f);
        const float dfly = fl * inv_res;

        #pragma unroll 4
        for (int j = 0; j < 32; j++, fly += dfly) {
            float4 r;
            float* rp = &r.x;
            #pragma unroll
            for (int k = 0; k < 4; k++) {
                float v = fly * izc[k] + off;                      // FFMA
                float d = wp[k][__float2int_rn(v) * CACHE_PITCH];  // F2I+IMAD+LDS
                float dk = d + (float)k * inv_res;                 // FADD (imm)
                float t = fminf(fabsf(zc0 - dk), trunc);           // FADD+FMNMX|.|
                rp[k] = fmaf(-(float)RES, t, 1.0f);                // FFMA
            }
            *reinterpret_cast<float4*>(ob + j * RES) = r;
        }
    } else {
        // ---- general fallback: per-voxel checked direct gather ----
        bool uok[4];
        #pragma unroll
        for (int k = 0; k < 4; k++) {
            float zck = zc0 - (float)k * inv_res;
            float u = flx * izc[k] + off;
            uok[k] = (u >= 0.0f) & (u <= wmax) & (zck > 0.0f);
            ui[k] = min(max(ui[k], 0), IMG - 1);
        }
        #pragma unroll 2
        for (int j = 0; j < 32; j++) {
            const float fly = fl * (((float)(iy0 + j) + 0.5f) * inv_res - 0.5f);
            float4 r;
            float* rp = &r.x;
            #pragma unroll
            for (int k = 0; k < 4; k++) {
                float zck = zc0 - (float)k * inv_res;
                float v = fly * izc[k] + off;
                bool ok = uok[k] & (v >= 0.0f) & (v <= wmax);
                float d = 0.0f;
                if (ok) {
                    int vi = min(max(__float2int_rn(v), 0), IMG - 1);
                    d = __ldg(ds + vi * IMG + ui[k]);
                }
                float val = fmaf(-(float)RES, fminf(fabsf(zck - d), trunc), 1.0f);
                rp[k] = (ok & (d > 0.0f)) ? val : 0.0f;
            }
            *reinterpret_cast<float4*>(ob + j * RES) = r;
        }
    }
}

extern "C" void kernel_launch(void* const* d_in, const int* in_sizes, int n_in,
                              void* d_out, int out_size)
{
    const float* depth = (const float*)d_in[0];
    const float* fl    = (const float*)d_in[1];
    const float* cd    = (const float*)d_in[2];
    float* out = (float*)d_out;

    const unsigned grid = NBATCH * 4 * 4 * 4;   // 1024 blocks (one full wave)
    backproj_kernel<<<grid, 256>>>(depth, fl, cd, out);
}

// round 15
// speedup vs baseline: 1.0790x; 1.0790x over previous
#include <cuda_runtime.h>

#define RES 128
#define IMG 480
#define NBATCH 16

#define CACHE_W 88       // max unaligned window width (validity check)
#define CACHE_H 56
#define CACHE_PITCH 88   // mult of 4 (16B-aligned float4 rows)

// Block: fixed b; ix in [ixo*32,+32), iz in [izo*32,+32), iy in [iyo*16,+16).
// 2048 blocks = 1.73 waves over 148 SMs x 8 resident: every SM busy, spread
// smoothed by work-stealing, wave transitions halved vs 4096-block version.
// Thread: ix = ixo*32 + w*4 + (lane>>3); iz quad = izo*32 + (lane&7)*4 .. +3.
// Inner loop / arithmetic byte-identical to the verified R12 baseline.

__global__ __launch_bounds__(256, 8)
void backproj_kernel(const float* __restrict__ depth,
                     const float* __restrict__ fl_arr,
                     const float* __restrict__ cd_arr,
                     float* __restrict__ out)
{
    __shared__ float win[CACHE_H * CACHE_PITCH];

    const int bid = blockIdx.x;          // 2048 blocks
    const int izo = bid & 3;
    const int ixo = (bid >> 2) & 3;
    const int iyo = (bid >> 4) & 7;
    const int b   = bid >> 7;

    const int tid  = threadIdx.x;
    const int lane = tid & 31;
    const int w    = tid >> 5;           // 0..7

    const float inv_res = 1.0f / (float)RES;
    const float off   = (IMG - 1) * 0.5f;   // 239.5
    const float wmax  = (float)(IMG - 1);   // 479
    const float trunc = inv_res;            // h = 1/128

    const float fl = __ldg(fl_arr + b);
    const float cd = __ldg(cd_arr + b);

    const int ix  = ixo * 32 + w * 4 + (lane >> 3);
    const int izb = izo * 32 + (lane & 7) * 4;
    const int iy0 = iyo * 16;

    // ---- per-thread prologue: 4 consecutive iz ----
    const float flx = fl * (((float)ix + 0.5f) * inv_res - 0.5f);
    const float zc0 = cd - (((float)izb + 0.5f) * inv_res - 0.5f);  // zc[k] = zc0 - k*h
    float izc[4];
    int   ui[4];
    #pragma unroll
    for (int k = 0; k < 4; k++) {
        izc[k] = 1.0f / (zc0 - (float)k * inv_res);
        ui[k]  = __float2int_rn(flx * izc[k] + off);
    }

    // ---- block-uniform corner bounds ----
    const float cx_lo = ((float)(ixo * 32)      + 0.5f) * inv_res - 0.5f;
    const float cx_hi = ((float)(ixo * 32 + 31) + 0.5f) * inv_res - 0.5f;
    const float cy_lo = ((float)(iy0)           + 0.5f) * inv_res - 0.5f;
    const float cy_hi = ((float)(iy0 + 15)      + 0.5f) * inv_res - 0.5f;
    const float zc_a  = cd - (((float)(izo * 32)      + 0.5f) * inv_res - 0.5f);
    const float zc_b  = cd - (((float)(izo * 32 + 31) + 0.5f) * inv_res - 0.5f);
    const float ia = 1.0f / zc_a, ib = 1.0f / zc_b;

    float u00 = fl * cx_lo * ia + off, u01 = fl * cx_lo * ib + off;
    float u10 = fl * cx_hi * ia + off, u11 = fl * cx_hi * ib + off;
    float v00 = fl * cy_lo * ia + off, v01 = fl * cy_lo * ib + off;
    float v10 = fl * cy_hi * ia + off, v11 = fl * cy_hi * ib + off;

    float umin = fminf(fminf(u00, u01), fminf(u10, u11));
    float umax = fmaxf(fmaxf(u00, u01), fmaxf(u10, u11));
    float vmin = fminf(fminf(v00, v01), fminf(v10, v11));
    float vmax = fmaxf(fmaxf(v00, v01), fmaxf(v10, v11));

    int u0 = max(0, (int)floorf(umin) - 1);
    int u1 = min(IMG - 1, (int)ceilf(umax) + 1);
    int v0 = max(0, (int)floorf(vmin) - 1);
    int v1 = min(IMG - 1, (int)ceilf(vmax) + 1);
    const int Wd = u1 - u0 + 1;
    const int Hd = v1 - v0 + 1;

    const bool all_valid =
        (fminf(zc_a, zc_b) > trunc) &
        (umin >= 0.01f) & (umax <= wmax - 0.01f) &
        (vmin >= 0.01f) & (vmax <= wmax - 0.01f) &
        (Wd <= CACHE_W) & (Hd <= CACHE_H);

    const float* __restrict__ ds = depth + (size_t)b * (IMG * IMG);
    float* __restrict__ ob = out + (((size_t)(b * RES + ix)) * RES + iy0) * RES + izb;

    if (all_valid) {
        // ---- float4 window fill: u0 aligned down to 4; warp per row stripe ----
        const int u0a = u0 & ~3;                     // 16B-aligned start
        const int W4  = (u1 - u0a + 4) >> 2;         // float4 count (<=22)
        for (int r = w; r < Hd; r += 8) {
            const float4* src = reinterpret_cast<const float4*>(ds + (v0 + r) * IMG + u0a);
            float4* dst = reinterpret_cast<float4*>(win + r * CACHE_PITCH);
            if (lane < W4) dst[lane] = __ldg(src + lane);
        }
        __syncthreads();

        // precomputed smem pointers: gather addr = wp[k] + vi*CACHE_PITCH
        const float* wp[4];
        #pragma unroll
        for (int k = 0; k < 4; k++)
            wp[k] = win + ((ui[k] - u0a) - v0 * CACHE_PITCH);

        float fly = fl * (((float)iy0 + 0.5f) * inv_res - 0.5f);
        const float dfly = fl * inv_res;

        #pragma unroll 4
        for (int j = 0; j < 16; j++, fly += dfly) {
            float4 r;
            float* rp = &r.x;
            #pragma unroll
            for (int k = 0; k < 4; k++) {
                float v = fly * izc[k] + off;                      // FFMA
                float d = wp[k][__float2int_rn(v) * CACHE_PITCH];  // F2I+IMAD+LDS
                float dk = d + (float)k * inv_res;                 // FADD (imm)
                float t = fminf(fabsf(zc0 - dk), trunc);           // FADD+FMNMX|.|
                rp[k] = fmaf(-(float)RES, t, 1.0f);                // FFMA
            }
            *reinterpret_cast<float4*>(ob + j * RES) = r;
        }
    } else {
        // ---- general fallback: per-voxel checked direct gather ----
        bool uok[4];
        #pragma unroll
        for (int k = 0; k < 4; k++) {
            float zck = zc0 - (float)k * inv_res;
            float u = flx * izc[k] + off;
            uok[k] = (u >= 0.0f) & (u <= wmax) & (zck > 0.0f);
            ui[k] = min(max(ui[k], 0), IMG - 1);
        }
        #pragma unroll 2
        for (int j = 0; j < 16; j++) {
            const float fly = fl * (((float)(iy0 + j) + 0.5f) * inv_res - 0.5f);
            float4 r;
            float* rp = &r.x;
            #pragma unroll
            for (int k = 0; k < 4; k++) {
                float zck = zc0 - (float)k * inv_res;
                float v = fly * izc[k] + off;
                bool ok = uok[k] & (v >= 0.0f) & (v <= wmax);
                float d = 0.0f;
                if (ok) {
                    int vi = min(max(__float2int_rn(v), 0), IMG - 1);
                    d = __ldg(ds + vi * IMG + ui[k]);
                }
                float val = fmaf(-(float)RES, fminf(fabsf(zck - d), trunc), 1.0f);
                rp[k] = (ok & (d > 0.0f)) ? val : 0.0f;
            }
            *reinterpret_cast<float4*>(ob + j * RES) = r;
        }
    }
}

extern "C" void kernel_launch(void* const* d_in, const int* in_sizes, int n_in,
                              void* d_out, int out_size)
{
    const float* depth = (const float*)d_in[0];
    const float* fl    = (const float*)d_in[1];
    const float* cd    = (const float*)d_in[2];
    float* out = (float*)d_out;

    const unsigned grid = NBATCH * 8 * 4 * 4;   // 2048 blocks (1.73 waves)
    backproj_kernel<<<grid, 256>>>(depth, fl, cd, out);
}

// round 16
// speedup vs baseline: 1.1801x; 1.0936x over previous
#include <cuda_runtime.h>

#define RES 128
#define IMG 480
#define NBATCH 16

#define CACHE_W 88       // max unaligned window width (validity check)
#define CACHE_H 56
#define CACHE_PITCH 100  // mod-32 = 4 -> vi*PITCH cycles 8 banks (verified layout)

// Block: fixed b; ix in [ixo*32,+32), iz in [izo*32,+32), iy in [iyo*16,+16).
// 2048 blocks = 1.73 waves over 148 SMs x 8 resident.
// Thread: ix = ixo*32 + w*4 + (lane>>3); iz quad = izo*32 + (lane&7)*4 .. +3.
// Inner arithmetic byte-identical to R12. Output stores use .cs streaming hint
// so the write-once 134MB stream doesn't evict the 14.7MB depth image from L2.

__global__ __launch_bounds__(256, 8)
void backproj_kernel(const float* __restrict__ depth,
                     const float* __restrict__ fl_arr,
                     const float* __restrict__ cd_arr,
                     float* __restrict__ out)
{
    __shared__ float win[CACHE_H * CACHE_PITCH];

    const int bid = blockIdx.x;          // 2048 blocks
    const int izo = bid & 3;
    const int ixo = (bid >> 2) & 3;
    const int iyo = (bid >> 4) & 7;
    const int b   = bid >> 7;

    const int tid  = threadIdx.x;
    const int lane = tid & 31;
    const int w    = tid >> 5;           // 0..7

    const float inv_res = 1.0f / (float)RES;
    const float off   = (IMG - 1) * 0.5f;   // 239.5
    const float wmax  = (float)(IMG - 1);   // 479
    const float trunc = inv_res;            // h = 1/128

    const float fl = __ldg(fl_arr + b);
    const float cd = __ldg(cd_arr + b);

    const int ix  = ixo * 32 + w * 4 + (lane >> 3);
    const int izb = izo * 32 + (lane & 7) * 4;
    const int iy0 = iyo * 16;

    // ---- per-thread prologue: 4 consecutive iz ----
    const float flx = fl * (((float)ix + 0.5f) * inv_res - 0.5f);
    const float zc0 = cd - (((float)izb + 0.5f) * inv_res - 0.5f);  // zc[k] = zc0 - k*h
    float izc[4];
    int   ui[4];
    #pragma unroll
    for (int k = 0; k < 4; k++) {
        izc[k] = 1.0f / (zc0 - (float)k * inv_res);
        ui[k]  = __float2int_rn(flx * izc[k] + off);
    }

    // ---- block-uniform corner bounds ----
    const float cx_lo = ((float)(ixo * 32)      + 0.5f) * inv_res - 0.5f;
    const float cx_hi = ((float)(ixo * 32 + 31) + 0.5f) * inv_res - 0.5f;
    const float cy_lo = ((float)(iy0)           + 0.5f) * inv_res - 0.5f;
    const float cy_hi = ((float)(iy0 + 15)      + 0.5f) * inv_res - 0.5f;
    const float zc_a  = cd - (((float)(izo * 32)      + 0.5f) * inv_res - 0.5f);
    const float zc_b  = cd - (((float)(izo * 32 + 31) + 0.5f) * inv_res - 0.5f);
    const float ia = 1.0f / zc_a, ib = 1.0f / zc_b;

    float u00 = fl * cx_lo * ia + off, u01 = fl * cx_lo * ib + off;
    float u10 = fl * cx_hi * ia + off, u11 = fl * cx_hi * ib + off;
    float v00 = fl * cy_lo * ia + off, v01 = fl * cy_lo * ib + off;
    float v10 = fl * cy_hi * ia + off, v11 = fl * cy_hi * ib + off;

    float umin = fminf(fminf(u00, u01), fminf(u10, u11));
    float umax = fmaxf(fmaxf(u00, u01), fmaxf(u10, u11));
    float vmin = fminf(fminf(v00, v01), fminf(v10, v11));
    float vmax = fmaxf(fmaxf(v00, v01), fmaxf(v10, v11));

    int u0 = max(0, (int)floorf(umin) - 1);
    int u1 = min(IMG - 1, (int)ceilf(umax) + 1);
    int v0 = max(0, (int)floorf(vmin) - 1);
    int v1 = min(IMG - 1, (int)ceilf(vmax) + 1);
    const int Wd = u1 - u0 + 1;
    const int Hd = v1 - v0 + 1;

    const bool all_valid =
        (fminf(zc_a, zc_b) > trunc) &
        (umin >= 0.01f) & (umax <= wmax - 0.01f) &
        (vmin >= 0.01f) & (vmax <= wmax - 0.01f) &
        (Wd <= CACHE_W) & (Hd <= CACHE_H);

    const float* __restrict__ ds = depth + (size_t)b * (IMG * IMG);
    float* __restrict__ ob = out + (((size_t)(b * RES + ix)) * RES + iy0) * RES + izb;

    if (all_valid) {
        // ---- float4 window fill: u0 aligned down to 4; warp per row stripe ----
        const int u0a = u0 & ~3;                     // 16B-aligned start
        const int W4  = (u1 - u0a + 4) >> 2;         // float4 count (<=23)
        for (int r = w; r < Hd; r += 8) {
            const float4* src = reinterpret_cast<const float4*>(ds + (v0 + r) * IMG + u0a);
            float4* dst = reinterpret_cast<float4*>(win + r * CACHE_PITCH);
            if (lane < W4) dst[lane] = __ldg(src + lane);
        }
        __syncthreads();

        // precomputed smem pointers: gather addr = wp[k] + vi*CACHE_PITCH
        const float* wp[4];
        #pragma unroll
        for (int k = 0; k < 4; k++)
            wp[k] = win + ((ui[k] - u0a) - v0 * CACHE_PITCH);

        float fly = fl * (((float)iy0 + 0.5f) * inv_res - 0.5f);
        const float dfly = fl * inv_res;

        #pragma unroll 4
        for (int j = 0; j < 16; j++, fly += dfly) {
            float4 r;
            float* rp = &r.x;
            #pragma unroll
            for (int k = 0; k < 4; k++) {
                float v = fly * izc[k] + off;                      // FFMA
                float d = wp[k][__float2int_rn(v) * CACHE_PITCH];  // F2I+IMAD+LDS
                float dk = d + (float)k * inv_res;                 // FADD (imm)
                float t = fminf(fabsf(zc0 - dk), trunc);           // FADD+FMNMX|.|
                rp[k] = fmaf(-(float)RES, t, 1.0f);                // FFMA
            }
            __stcs(reinterpret_cast<float4*>(ob + j * RES), r);    // STG.128.CS
        }
    } else {
        // ---- general fallback: per-voxel checked direct gather ----
        bool uok[4];
        #pragma unroll
        for (int k = 0; k < 4; k++) {
            float zck = zc0 - (float)k * inv_res;
            float u = flx * izc[k] + off;
            uok[k] = (u >= 0.0f) & (u <= wmax) & (zck > 0.0f);
            ui[k] = min(max(ui[k], 0), IMG - 1);
        }
        #pragma unroll 2
        for (int j = 0; j < 16; j++) {
            const float fly = fl * (((float)(iy0 + j) + 0.5f) * inv_res - 0.5f);
            float4 r;
            float* rp = &r.x;
            #pragma unroll
            for (int k = 0; k < 4; k++) {
                float zck = zc0 - (float)k * inv_res;
                float v = fly * izc[k] + off;
                bool ok = uok[k] & (v >= 0.0f) & (v <= wmax);
                float d = 0.0f;
                if (ok) {
                    int vi = min(max(__float2int_rn(v), 0), IMG - 1);
                    d = __ldg(ds + vi * IMG + ui[k]);
                }
                float val = fmaf(-(float)RES, fminf(fabsf(zck - d), trunc), 1.0f);
                rp[k] = (ok & (d > 0.0f)) ? val : 0.0f;
            }
            __stcs(reinterpret_cast<float4*>(ob + j * RES), r);
        }
    }
}

extern "C" void kernel_launch(void* const* d_in, const int* in_sizes, int n_in,
                              void* d_out, int out_size)
{
    const float* depth = (const float*)d_in[0];
    const float* fl    = (const float*)d_in[1];
    const float* cd    = (const float*)d_in[2];
    float* out = (float*)d_out;

    const unsigned grid = NBATCH * 8 * 4 * 4;   // 2048 blocks (1.73 waves)
    backproj_kernel<<<grid, 256>>>(depth, fl, cd, out);
}